// round 9
// baseline (speedup 1.0000x reference)
#include <cuda_runtime.h>
#include <cuda_bf16.h>
#include <cstdint>

// Problem constants (B=256, N=128, D=512)
#define BN    32768
#define DIM   512

// ---------------- device scratch (no allocations allowed) ----------------
__device__ __nv_bfloat16 g_xb[BN * DIM];     // bf16 copy of x (33.5 MB, fits L2)
__device__ float  g_E4[4][DIM * DIM];        // 4 e-split partials of E = 0.5*diag(r) - V V^T
__device__ double g_S;                       // sum G .* E  (the interaction scalar)
__device__ unsigned g_cnt;                   // k_gram completion counter

__device__ const int c_mt[10] = {0,0,0,0,1,1,1,2,2,3};
__device__ const int c_nt[10] = {0,1,2,3,1,2,3,2,3,3};

// ---------------- helpers ----------------
__device__ __forceinline__ unsigned smem_u32(const void* p) {
    return (unsigned)__cvta_generic_to_shared(p);
}
__device__ __forceinline__ unsigned pack_bf16x2(float a, float b) {
    __nv_bfloat162 h = __floats2bfloat162_rn(a, b);
    return *reinterpret_cast<unsigned*>(&h);
}
__device__ __forceinline__ void ldsm4t(unsigned* r, unsigned addr) {
    asm volatile("ldmatrix.sync.aligned.m8n8.x4.trans.shared.b16 {%0,%1,%2,%3}, [%4];"
                 : "=r"(r[0]), "=r"(r[1]), "=r"(r[2]), "=r"(r[3])
                 : "r"(addr));
}
__device__ __forceinline__ void mma16816(float* c, const unsigned* a, unsigned b0, unsigned b1) {
    asm volatile(
        "mma.sync.aligned.m16n8k16.row.col.f32.bf16.bf16.f32 "
        "{%0,%1,%2,%3}, {%4,%5,%6,%7}, {%8,%9}, {%0,%1,%2,%3};"
        : "+f"(c[0]), "+f"(c[1]), "+f"(c[2]), "+f"(c[3])
        : "r"(a[0]), "r"(a[1]), "r"(a[2]), "r"(a[3]), "r"(b0), "r"(b1));
}
__device__ __forceinline__ void cpasync16(unsigned saddr, const void* g) {
    asm volatile("cp.async.cg.shared.global [%0], [%1], 16;" :: "r"(saddr), "l"(g));
}
__device__ __forceinline__ void cp_commit() {
    asm volatile("cp.async.commit_group;");
}
template <int N>
__device__ __forceinline__ void cp_wait() {
    asm volatile("cp.async.wait_group %0;" :: "n"(N));
}

// ---------------- K1: merged prep ---------------------------------------
// blocks [0,256):   E partials (64 tiles x 4 e-splits) -> plain stores to g_E4[es]
// blocks [256,2304): linear part + bf16 conversion (16 rows per block)
__global__ __launch_bounds__(256) void k_prep(const float* __restrict__ x,
                                              const float* __restrict__ W,
                                              const float* __restrict__ bias,
                                              const float* __restrict__ V,
                                              float* __restrict__ out) {
    __shared__ float sVa[32 * 68];
    __shared__ float sVb[32 * 68];
    const int tid = threadIdx.x;
    const int blk = blockIdx.x;

    if (blk < 256) {
        // ---------- E tile partial (e-range of 128) ----------
        if (blk == 0 && tid == 0) { g_S = 0.0; g_cnt = 0u; }
        const int tile = blk >> 2, es = blk & 3;
        const int di = (tile >> 3) * 64, dj = (tile & 7) * 64;
        const int e0 = es * 128;
        const int tr = tid >> 4, tc = tid & 15;

        float acc[4][4];
#pragma unroll
        for (int i = 0; i < 4; i++)
#pragma unroll
            for (int j = 0; j < 4; j++) acc[i][j] = 0.f;

        for (int ch = 0; ch < 4; ch++) {           // 4 chunks of 32 e-values
            __syncthreads();
#pragma unroll
            for (int i = 0; i < 8; i++) {
                int idx = tid + i * 256;
                int rr = idx >> 5, cc = idx & 31;
                sVa[cc * 68 + rr] = V[(size_t)(di + rr) * DIM + e0 + ch * 32 + cc];
                sVb[cc * 68 + rr] = V[(size_t)(dj + rr) * DIM + e0 + ch * 32 + cc];
            }
            __syncthreads();
#pragma unroll 4
            for (int ec = 0; ec < 32; ec++) {
                float4 av = reinterpret_cast<const float4*>(sVa)[ec * 17 + tr];
                float4 bv = reinterpret_cast<const float4*>(sVb)[ec * 17 + tc];
                float a4[4] = {av.x, av.y, av.z, av.w};
                float b4[4] = {bv.x, bv.y, bv.z, bv.w};
#pragma unroll
                for (int i = 0; i < 4; i++)
#pragma unroll
                    for (int j = 0; j < 4; j++) acc[i][j] += a4[i] * b4[j];
            }
        }
        // partial of E = 0.5*diag(r) - C ; on diagonal the partial is -0.5*c
        float* Edst = g_E4[es];
#pragma unroll
        for (int i = 0; i < 4; i++) {
            int row = di + tr * 4 + i;
            float ev[4];
#pragma unroll
            for (int j = 0; j < 4; j++) {
                int col = dj + tc * 4 + j;
                float c = acc[i][j];
                ev[j] = (row == col) ? (-0.5f * c) : (-c);
            }
            float4 e = {ev[0], ev[1], ev[2], ev[3]};
            *reinterpret_cast<float4*>(&Edst[(size_t)row * DIM + dj + tc * 4]) = e;
        }
    } else {
        // ---------- linear + bf16 convert : 16 rows per CTA (R6 form) ----------
        float* sW = sVa;   // reuse smem
        for (int i = tid; i < DIM; i += 256) sW[i] = W[i];
        __syncthreads();

        const int warp = tid >> 5, lane = tid & 31;
        const int rbase = (blk - 256) * 16 + warp * 2;   // 2048 blocks * 16 rows
        const float4* wr = reinterpret_cast<const float4*>(sW);
        const float4 w0 = wr[2 * lane],      w1 = wr[2 * lane + 1];
        const float4 w2 = wr[64 + 2 * lane], w3 = wr[64 + 2 * lane + 1];

#pragma unroll
        for (int r = 0; r < 2; r++) {
            const int row = rbase + r;
            const float4* xr = reinterpret_cast<const float4*>(x + (size_t)row * DIM);
            uint4* xbr = reinterpret_cast<uint4*>(g_xb + (size_t)row * DIM);
            float4 a0 = xr[2 * lane], a1 = xr[2 * lane + 1];
            float4 a2 = xr[64 + 2 * lane], a3 = xr[64 + 2 * lane + 1];

            uint4 p0, p1;
            p0.x = pack_bf16x2(a0.x, a0.y); p0.y = pack_bf16x2(a0.z, a0.w);
            p0.z = pack_bf16x2(a1.x, a1.y); p0.w = pack_bf16x2(a1.z, a1.w);
            p1.x = pack_bf16x2(a2.x, a2.y); p1.y = pack_bf16x2(a2.z, a2.w);
            p1.z = pack_bf16x2(a3.x, a3.y); p1.w = pack_bf16x2(a3.z, a3.w);
            xbr[lane] = p0;
            xbr[32 + lane] = p1;

            float s0 = a0.x * w0.x + a0.y * w0.y + a0.z * w0.z + a0.w * w0.w;
            float s1 = a1.x * w1.x + a1.y * w1.y + a1.z * w1.z + a1.w * w1.w;
            float s2 = a2.x * w2.x + a2.y * w2.y + a2.z * w2.z + a2.w * w2.w;
            float s3 = a3.x * w3.x + a3.y * w3.y + a3.z * w3.z + a3.w * w3.w;
            float s = (s0 + s1) + (s2 + s3);
#pragma unroll
            for (int off = 16; off; off >>= 1) s += __shfl_xor_sync(0xffffffffu, s, off);
            if (lane == 0) out[row] = s + bias[0];
        }
    }
}

// ---------------- K2: Gram tiles (bf16 mma, cp.async) + trace epilogue ---
// 10 upper-triangular 128x128 tiles x 28 k-splits = 280 CTAs (2 per SM).
// Epilogue sums the 4 E partial buffers on load. Last CTA broadcasts scalar.
#define TKB 32
#define LDP 136           // bf16 pitch: 272B row stride -> conflict-free ldsm
#define NSPLIT 28
#define NBLK  (10 * NSPLIT)
#define NCHUNK (BN / TKB) // 1024

__global__ __launch_bounds__(256, 2) void k_gram(float* __restrict__ out) {
    __shared__ __align__(16) __nv_bfloat16 sA[2][TKB * LDP];
    __shared__ __align__(16) __nv_bfloat16 sB[2][TKB * LDP];
    __shared__ float red[256];
    __shared__ int slast;
    __shared__ double sS;

    const int tid  = threadIdx.x;
    const int bid  = blockIdx.x;
    const int tile = bid % 10;
    const int ks   = bid / 10;
    const int mt = c_mt[tile], nt = c_nt[tile];
    const bool diag = (mt == nt);
    const int m0 = mt * 128, n0 = nt * 128;
    const int ch0 = (ks * NCHUNK) / NSPLIT;
    const int ch1 = ((ks + 1) * NCHUNK) / NSPLIT;
    const int k0  = ch0 * TKB;
    const int nst = ch1 - ch0;            // 36 or 37 stages

    const int lane = tid & 31, warp = tid >> 5;
    const int wm0 = (warp >> 2) * 64;
    const int wn0 = (warp & 3) * 32;

    // ldmatrix lane mapping
    const int sub = lane >> 3, r8 = lane & 7;
    const int lmk = r8 + ((sub >> 1) << 3);
    const int lmc = (sub & 1) << 3;
    const unsigned lmoff = (unsigned)((lmk * LDP + lmc) * 2);

    // cp.async mapping: 512 16B-chunks per buffer; 2 per thread.
    const int r0c = tid >> 4,         c0c = tid & 15;
    const int r1c = (tid + 256) >> 4, c1c = tid & 15;
    const unsigned soff0 = (unsigned)(r0c * (LDP * 2) + c0c * 16);
    const unsigned soff1 = (unsigned)(r1c * (LDP * 2) + c1c * 16);
    const char* gA0 = (const char*)(g_xb + (size_t)(k0 + r0c) * DIM + m0) + c0c * 16;
    const char* gA1 = (const char*)(g_xb + (size_t)(k0 + r1c) * DIM + m0) + c1c * 16;
    const char* gB0 = (const char*)(g_xb + (size_t)(k0 + r0c) * DIM + n0) + c0c * 16;
    const char* gB1 = (const char*)(g_xb + (size_t)(k0 + r1c) * DIM + n0) + c1c * 16;
    const unsigned sAb[2] = { smem_u32(&sA[0][0]), smem_u32(&sA[1][0]) };
    const unsigned sBb[2] = { smem_u32(&sB[0][0]), smem_u32(&sB[1][0]) };

    auto issue = [&](int s) {
        const int buf = s & 1;
        const size_t go = (size_t)s * (TKB * DIM * 2);   // bytes per stage
        cpasync16(sAb[buf] + soff0, gA0 + go);
        cpasync16(sAb[buf] + soff1, gA1 + go);
        if (!diag) {
            cpasync16(sBb[buf] + soff0, gB0 + go);
            cpasync16(sBb[buf] + soff1, gB1 + go);
        }
    };

    float acc[4][4][4];
#pragma unroll
    for (int i = 0; i < 4; i++)
#pragma unroll
        for (int j = 0; j < 4; j++)
#pragma unroll
            for (int q = 0; q < 4; q++) acc[i][j][q] = 0.f;

    issue(0);
    cp_commit();

    for (int s = 0; s < nst; s++) {
        const int buf = s & 1;
        if (s + 1 < nst) {
            issue(s + 1);
            cp_commit();
            cp_wait<1>();
        } else {
            cp_wait<0>();
        }
        __syncthreads();

        const unsigned baseA = sAb[buf] + lmoff;
        const unsigned baseB = (diag ? sAb[buf] : sBb[buf]) + lmoff;
#pragma unroll
        for (int kk = 0; kk < TKB; kk += 16) {
            unsigned afr[4][4];
#pragma unroll
            for (int mi = 0; mi < 4; mi++)
                ldsm4t(afr[mi], baseA + (unsigned)((kk * LDP + wm0 + mi * 16) * 2));
            unsigned bq[2][4];
#pragma unroll
            for (int nb = 0; nb < 2; nb++)
                ldsm4t(bq[nb], baseB + (unsigned)((kk * LDP + wn0 + nb * 16) * 2));
#pragma unroll
            for (int mi = 0; mi < 4; mi++) {
                mma16816(acc[mi][0], afr[mi], bq[0][0], bq[0][2]);
                mma16816(acc[mi][1], afr[mi], bq[0][1], bq[0][3]);
                mma16816(acc[mi][2], afr[mi], bq[1][0], bq[1][2]);
                mma16816(acc[mi][3], afr[mi], bq[1][1], bq[1][3]);
            }
        }
        __syncthreads();
    }

    // ---- fused trace epilogue: partial = sum(acc .* E_tile), E = sum of 4 partials ----
    const int g = lane >> 2, t4 = lane & 3;
    float fsum = 0.f;
#pragma unroll
    for (int mi = 0; mi < 4; mi++) {
#pragma unroll
        for (int ni = 0; ni < 4; ni++) {
            int row0 = m0 + wm0 + mi * 16 + g;
            int col0 = n0 + wn0 + ni * 8 + 2 * t4;
            size_t i0 = (size_t)row0 * DIM + col0;
            size_t i1 = (size_t)(row0 + 8) * DIM + col0;
            float ex = 0.f, ey = 0.f, fx = 0.f, fy = 0.f;
#pragma unroll
            for (int es = 0; es < 4; es++) {
                float2 e0 = *reinterpret_cast<const float2*>(&g_E4[es][i0]);
                float2 e1 = *reinterpret_cast<const float2*>(&g_E4[es][i1]);
                ex += e0.x; ey += e0.y;
                fx += e1.x; fy += e1.y;
            }
            fsum += acc[mi][ni][0] * ex + acc[mi][ni][1] * ey
                  + acc[mi][ni][2] * fx + acc[mi][ni][3] * fy;
        }
    }
    red[tid] = fsum;
    __syncthreads();
    for (int o = 128; o; o >>= 1) {
        if (tid < o) red[tid] += red[tid + o];
        __syncthreads();
    }
    if (tid == 0) {
        double w = diag ? 1.0 : 2.0;   // symmetry: off-diagonal tiles counted twice
        atomicAdd(&g_S, w * (double)red[0]);
        __threadfence();
        unsigned old = atomicAdd(&g_cnt, 1u);
        slast = (old == NBLK - 1) ? 1 : 0;
        if (slast) sS = atomicAdd(&g_S, 0.0);    // all 280 contributions visible
    }
    __syncthreads();

    // ---- last CTA broadcasts the interaction scalar into out[] ----
    if (slast) {
        const float I = (float)sS;
        float4* o4 = reinterpret_cast<float4*>(out);
#pragma unroll 4
        for (int i = tid; i < BN / 4; i += 256) {
            float4 v = o4[i];
            v.x += I; v.y += I; v.z += I; v.w += I;
            o4[i] = v;
        }
    }
}

// ---------------- launch ----------------
extern "C" void kernel_launch(void* const* d_in, const int* in_sizes, int n_in,
                              void* d_out, int out_size) {
    const float* x = (const float*)d_in[0];   // [256,128,512]
    const float* W = (const float*)d_in[1];   // [1,512]
    const float* b = (const float*)d_in[2];   // [1]
    const float* V = (const float*)d_in[3];   // [512,512]
    float* out = (float*)d_out;               // [32768,1]

    k_prep <<<256 + BN / 16, 256>>>(x, W, b, V, out);
    k_gram <<<NBLK, 256>>>(out);
}

// round 10
// speedup vs baseline: 1.0263x; 1.0263x over previous
#include <cuda_runtime.h>
#include <cuda_bf16.h>
#include <cstdint>

// Problem constants (B=256, N=128, D=512)
#define BN    32768
#define DIM   512

// ---------------- device scratch (no allocations allowed) ----------------
__device__ __nv_bfloat16 g_xb[BN * DIM];     // bf16 copy of x (33.5 MB, fits L2)
__device__ float  g_E4[4][DIM * DIM];        // 4 e-split partials of E = 0.5*diag(r) - V V^T
__device__ double g_S;                       // sum G .* E  (the interaction scalar)
__device__ unsigned g_cnt;                   // k_gram completion counter

__device__ const int c_mt[10] = {0,0,0,0,1,1,1,2,2,3};
__device__ const int c_nt[10] = {0,1,2,3,1,2,3,2,3,3};

// ---------------- helpers ----------------
__device__ __forceinline__ unsigned smem_u32(const void* p) {
    return (unsigned)__cvta_generic_to_shared(p);
}
__device__ __forceinline__ unsigned pack_bf16x2(float a, float b) {
    __nv_bfloat162 h = __floats2bfloat162_rn(a, b);
    return *reinterpret_cast<unsigned*>(&h);
}
__device__ __forceinline__ void ldsm4t(unsigned* r, unsigned addr) {
    asm volatile("ldmatrix.sync.aligned.m8n8.x4.trans.shared.b16 {%0,%1,%2,%3}, [%4];"
                 : "=r"(r[0]), "=r"(r[1]), "=r"(r[2]), "=r"(r[3])
                 : "r"(addr));
}
__device__ __forceinline__ void mma16816(float* c, const unsigned* a, unsigned b0, unsigned b1) {
    asm volatile(
        "mma.sync.aligned.m16n8k16.row.col.f32.bf16.bf16.f32 "
        "{%0,%1,%2,%3}, {%4,%5,%6,%7}, {%8,%9}, {%0,%1,%2,%3};"
        : "+f"(c[0]), "+f"(c[1]), "+f"(c[2]), "+f"(c[3])
        : "r"(a[0]), "r"(a[1]), "r"(a[2]), "r"(a[3]), "r"(b0), "r"(b1));
}
__device__ __forceinline__ void cpasync16(unsigned saddr, const void* g) {
    asm volatile("cp.async.cg.shared.global [%0], [%1], 16;" :: "r"(saddr), "l"(g));
}
__device__ __forceinline__ void cp_commit() {
    asm volatile("cp.async.commit_group;");
}
template <int N>
__device__ __forceinline__ void cp_wait() {
    asm volatile("cp.async.wait_group %0;" :: "n"(N));
}

// ---------------- K1: merged prep (unchanged, R9-passing form) ----------
// blocks [0,256):   E partials (64 tiles x 4 e-splits) -> plain stores to g_E4[es]
// blocks [256,2304): linear part + bf16 conversion (16 rows per block)
__global__ __launch_bounds__(256) void k_prep(const float* __restrict__ x,
                                              const float* __restrict__ W,
                                              const float* __restrict__ bias,
                                              const float* __restrict__ V,
                                              float* __restrict__ out) {
    __shared__ float sVa[32 * 68];
    __shared__ float sVb[32 * 68];
    const int tid = threadIdx.x;
    const int blk = blockIdx.x;

    if (blk < 256) {
        if (blk == 0 && tid == 0) { g_S = 0.0; g_cnt = 0u; }
        const int tile = blk >> 2, es = blk & 3;
        const int di = (tile >> 3) * 64, dj = (tile & 7) * 64;
        const int e0 = es * 128;
        const int tr = tid >> 4, tc = tid & 15;

        float acc[4][4];
#pragma unroll
        for (int i = 0; i < 4; i++)
#pragma unroll
            for (int j = 0; j < 4; j++) acc[i][j] = 0.f;

        for (int ch = 0; ch < 4; ch++) {
            __syncthreads();
#pragma unroll
            for (int i = 0; i < 8; i++) {
                int idx = tid + i * 256;
                int rr = idx >> 5, cc = idx & 31;
                sVa[cc * 68 + rr] = V[(size_t)(di + rr) * DIM + e0 + ch * 32 + cc];
                sVb[cc * 68 + rr] = V[(size_t)(dj + rr) * DIM + e0 + ch * 32 + cc];
            }
            __syncthreads();
#pragma unroll 4
            for (int ec = 0; ec < 32; ec++) {
                float4 av = reinterpret_cast<const float4*>(sVa)[ec * 17 + tr];
                float4 bv = reinterpret_cast<const float4*>(sVb)[ec * 17 + tc];
                float a4[4] = {av.x, av.y, av.z, av.w};
                float b4[4] = {bv.x, bv.y, bv.z, bv.w};
#pragma unroll
                for (int i = 0; i < 4; i++)
#pragma unroll
                    for (int j = 0; j < 4; j++) acc[i][j] += a4[i] * b4[j];
            }
        }
        float* Edst = g_E4[es];
#pragma unroll
        for (int i = 0; i < 4; i++) {
            int row = di + tr * 4 + i;
            float ev[4];
#pragma unroll
            for (int j = 0; j < 4; j++) {
                int col = dj + tc * 4 + j;
                float c = acc[i][j];
                ev[j] = (row == col) ? (-0.5f * c) : (-c);
            }
            float4 e = {ev[0], ev[1], ev[2], ev[3]};
            *reinterpret_cast<float4*>(&Edst[(size_t)row * DIM + dj + tc * 4]) = e;
        }
    } else {
        float* sW = sVa;
        for (int i = tid; i < DIM; i += 256) sW[i] = W[i];
        __syncthreads();

        const int warp = tid >> 5, lane = tid & 31;
        const int rbase = (blk - 256) * 16 + warp * 2;
        const float4* wr = reinterpret_cast<const float4*>(sW);
        const float4 w0 = wr[2 * lane],      w1 = wr[2 * lane + 1];
        const float4 w2 = wr[64 + 2 * lane], w3 = wr[64 + 2 * lane + 1];

#pragma unroll
        for (int r = 0; r < 2; r++) {
            const int row = rbase + r;
            const float4* xr = reinterpret_cast<const float4*>(x + (size_t)row * DIM);
            uint4* xbr = reinterpret_cast<uint4*>(g_xb + (size_t)row * DIM);
            float4 a0 = xr[2 * lane], a1 = xr[2 * lane + 1];
            float4 a2 = xr[64 + 2 * lane], a3 = xr[64 + 2 * lane + 1];

            uint4 p0, p1;
            p0.x = pack_bf16x2(a0.x, a0.y); p0.y = pack_bf16x2(a0.z, a0.w);
            p0.z = pack_bf16x2(a1.x, a1.y); p0.w = pack_bf16x2(a1.z, a1.w);
            p1.x = pack_bf16x2(a2.x, a2.y); p1.y = pack_bf16x2(a2.z, a2.w);
            p1.z = pack_bf16x2(a3.x, a3.y); p1.w = pack_bf16x2(a3.z, a3.w);
            xbr[lane] = p0;
            xbr[32 + lane] = p1;

            float s0 = a0.x * w0.x + a0.y * w0.y + a0.z * w0.z + a0.w * w0.w;
            float s1 = a1.x * w1.x + a1.y * w1.y + a1.z * w1.z + a1.w * w1.w;
            float s2 = a2.x * w2.x + a2.y * w2.y + a2.z * w2.z + a2.w * w2.w;
            float s3 = a3.x * w3.x + a3.y * w3.y + a3.z * w3.z + a3.w * w3.w;
            float s = (s0 + s1) + (s2 + s3);
#pragma unroll
            for (int off = 16; off; off >>= 1) s += __shfl_xor_sync(0xffffffffu, s, off);
            if (lane == 0) out[row] = s + bias[0];
        }
    }
}

// ---------------- K2: Gram tiles — 4-stage cp.async pipeline -------------
// 10 upper-triangular 128x128 tiles x 28 k-splits = 280 CTAs (2 per SM).
// TKB=16 rows per stage, 4 smem buffers, loads issued 3 stages ahead,
// ONE __syncthreads per stage. Epilogue: dot with E (sum of 4 partials);
// last CTA broadcasts the scalar into out[].
#define TKB 16
#define LDP 136           // bf16 pitch: 272B row stride -> conflict-free ldsm
#define NSTG 4
#define NSPLIT 28
#define NBLK  (10 * NSPLIT)
#define NCHUNK (BN / TKB) // 2048

__global__ __launch_bounds__(256, 2) void k_gram(float* __restrict__ out) {
    __shared__ __align__(16) __nv_bfloat16 sA[NSTG][TKB * LDP];
    __shared__ __align__(16) __nv_bfloat16 sB[NSTG][TKB * LDP];
    __shared__ float red[256];
    __shared__ int slast;
    __shared__ double sS;

    const int tid  = threadIdx.x;
    const int bid  = blockIdx.x;
    const int tile = bid % 10;
    const int ks   = bid / 10;
    const int mt = c_mt[tile], nt = c_nt[tile];
    const bool diag = (mt == nt);
    const int m0 = mt * 128, n0 = nt * 128;
    const int ch0 = (ks * NCHUNK) / NSPLIT;
    const int ch1 = ((ks + 1) * NCHUNK) / NSPLIT;
    const int k0  = ch0 * TKB;
    const int nst = ch1 - ch0;            // 73 or 74 stages

    const int lane = tid & 31, warp = tid >> 5;
    const int wm0 = (warp >> 2) * 64;
    const int wn0 = (warp & 3) * 32;

    // ldmatrix lane mapping
    const int sub = lane >> 3, r8 = lane & 7;
    const int lmk = r8 + ((sub >> 1) << 3);
    const int lmc = (sub & 1) << 3;
    const unsigned lmoff = (unsigned)((lmk * LDP + lmc) * 2);

    // cp.async mapping: 256 16B-chunks per buffer; 1 per thread per matrix.
    const int rc = tid >> 4, cc16 = tid & 15;
    const unsigned soff = (unsigned)(rc * (LDP * 2) + cc16 * 16);
    const char* gA = (const char*)(g_xb + (size_t)(k0 + rc) * DIM + m0) + cc16 * 16;
    const char* gB = (const char*)(g_xb + (size_t)(k0 + rc) * DIM + n0) + cc16 * 16;
    unsigned sAb[NSTG], sBb[NSTG];
#pragma unroll
    for (int i = 0; i < NSTG; i++) {
        sAb[i] = smem_u32(&sA[i][0]);
        sBb[i] = smem_u32(&sB[i][0]);
    }

    auto issue = [&](int s) {
        const int buf = s & (NSTG - 1);
        const size_t go = (size_t)s * (TKB * DIM * 2);   // bytes per stage
        cpasync16(sAb[buf] + soff, gA + go);
        if (!diag) cpasync16(sBb[buf] + soff, gB + go);
        cp_commit();
    };

    float acc[4][4][4];
#pragma unroll
    for (int i = 0; i < 4; i++)
#pragma unroll
        for (int j = 0; j < 4; j++)
#pragma unroll
            for (int q = 0; q < 4; q++) acc[i][j][q] = 0.f;

    // prologue: 3 stages in flight
    issue(0);
    issue(1);
    issue(2);

    for (int s = 0; s < nst; s++) {
        const int buf = s & (NSTG - 1);
        // wait until group s has landed (groups outstanding: s..min(s+2,nst-1))
        if (s + 2 < nst)      cp_wait<2>();
        else if (s + 1 < nst) cp_wait<1>();
        else                  cp_wait<0>();
        __syncthreads();   // buffer s visible to all; all threads done with buffer s-1

        const unsigned baseA = sAb[buf] + lmoff;
        const unsigned baseB = (diag ? sAb[buf] : sBb[buf]) + lmoff;
        unsigned afr[4][4];
#pragma unroll
        for (int mi = 0; mi < 4; mi++)
            ldsm4t(afr[mi], baseA + (unsigned)((wm0 + mi * 16) * 2));
        unsigned bq[2][4];
#pragma unroll
        for (int nb = 0; nb < 2; nb++)
            ldsm4t(bq[nb], baseB + (unsigned)((wn0 + nb * 16) * 2));
#pragma unroll
        for (int mi = 0; mi < 4; mi++) {
            mma16816(acc[mi][0], afr[mi], bq[0][0], bq[0][2]);
            mma16816(acc[mi][1], afr[mi], bq[0][1], bq[0][3]);
            mma16816(acc[mi][2], afr[mi], bq[1][0], bq[1][2]);
            mma16816(acc[mi][3], afr[mi], bq[1][1], bq[1][3]);
        }

        // refill: overwrites buffer of stage s-1; all threads passed this
        // iteration's __syncthreads, hence finished reading it.
        if (s + 3 < nst) issue(s + 3);
    }

    // ---- fused trace epilogue: partial = sum(acc .* E_tile), E = sum of 4 partials ----
    const int g = lane >> 2, t4 = lane & 3;
    float fsum = 0.f;
#pragma unroll
    for (int mi = 0; mi < 4; mi++) {
#pragma unroll
        for (int ni = 0; ni < 4; ni++) {
            int row0 = m0 + wm0 + mi * 16 + g;
            int col0 = n0 + wn0 + ni * 8 + 2 * t4;
            size_t i0 = (size_t)row0 * DIM + col0;
            size_t i1 = (size_t)(row0 + 8) * DIM + col0;
            float ex = 0.f, ey = 0.f, fx = 0.f, fy = 0.f;
#pragma unroll
            for (int es = 0; es < 4; es++) {
                float2 e0 = *reinterpret_cast<const float2*>(&g_E4[es][i0]);
                float2 e1 = *reinterpret_cast<const float2*>(&g_E4[es][i1]);
                ex += e0.x; ey += e0.y;
                fx += e1.x; fy += e1.y;
            }
            fsum += acc[mi][ni][0] * ex + acc[mi][ni][1] * ey
                  + acc[mi][ni][2] * fx + acc[mi][ni][3] * fy;
        }
    }
    red[tid] = fsum;
    __syncthreads();
    for (int o = 128; o; o >>= 1) {
        if (tid < o) red[tid] += red[tid + o];
        __syncthreads();
    }
    if (tid == 0) {
        double w = diag ? 1.0 : 2.0;   // symmetry: off-diagonal tiles counted twice
        atomicAdd(&g_S, w * (double)red[0]);
        __threadfence();
        unsigned old = atomicAdd(&g_cnt, 1u);
        slast = (old == NBLK - 1) ? 1 : 0;
        if (slast) sS = atomicAdd(&g_S, 0.0);    // all 280 contributions visible
    }
    __syncthreads();

    // ---- last CTA broadcasts the interaction scalar into out[] ----
    if (slast) {
        const float I = (float)sS;
        float4* o4 = reinterpret_cast<float4*>(out);
#pragma unroll 4
        for (int i = tid; i < BN / 4; i += 256) {
            float4 v = o4[i];
            v.x += I; v.y += I; v.z += I; v.w += I;
            o4[i] = v;
        }
    }
}

// ---------------- launch ----------------
extern "C" void kernel_launch(void* const* d_in, const int* in_sizes, int n_in,
                              void* d_out, int out_size) {
    const float* x = (const float*)d_in[0];   // [256,128,512]
    const float* W = (const float*)d_in[1];   // [1,512]
    const float* b = (const float*)d_in[2];   // [1]
    const float* V = (const float*)d_in[3];   // [512,512]
    float* out = (float*)d_out;               // [32768,1]

    k_prep <<<256 + BN / 16, 256>>>(x, W, b, V, out);
    k_gram <<<NBLK, 256>>>(out);
}